// round 1
// baseline (speedup 1.0000x reference)
#include <cuda_runtime.h>
#include <math.h>

// Problem constants (fixed by setup_inputs)
#define BB 8
#define NN 2000
#define HH 128
#define KK 32
#define MM (BB * NN)        // 16000 rows
#define KDIM 384            // concat [in_agg | out_agg | h]
#define GD 512              // 128 d * 4 gates

// Scratch (device globals; no allocation allowed)
__device__ float g_X[MM * KDIM];     // concatenated GEMM input per layer
__device__ float g_Wp[KDIM * GD];    // W_cat in [k][d][g] layout
__device__ float g_h[MM * HH];       // h after layer 1
__device__ float g_c[MM * HH];       // cell state scratch

// ---------------------------------------------------------------------------
// Build W_cat[k][d][g]:
//   k in [0,128)   -> w_in[g][k][d]
//   k in [128,256) -> w_out[g][k-128][d]
//   k in [256,384) -> u_in[g][k-256][d] + u_out[g][k-256][d]
// ---------------------------------------------------------------------------
__global__ void prep_kernel(const float* __restrict__ w_in,
                            const float* __restrict__ w_out,
                            const float* __restrict__ u_in,
                            const float* __restrict__ u_out) {
    int idx = blockIdx.x * blockDim.x + threadIdx.x;   // 196608 exact
    int k = idx >> 9;
    int rem = idx & 511;
    int d = rem >> 2;
    int g = rem & 3;
    float v;
    if (k < 128) {
        v = w_in[(g * 128 + k) * 128 + d];
    } else if (k < 256) {
        v = w_out[(g * 128 + (k - 128)) * 128 + d];
    } else {
        int kk = k - 256;
        v = u_in[(g * 128 + kk) * 128 + d] + u_out[(g * 128 + kk) * 128 + d];
    }
    g_Wp[idx] = v;
}

// ---------------------------------------------------------------------------
// Aggregation: one warp per node. Gathers K=32 neighbor rows for both in/out
// edge sets, masked-sums them, and writes the concatenated X row:
//   X[bn][0:128]   = in_agg
//   X[bn][128:256] = out_agg
//   X[bn][256:384] = h
// ---------------------------------------------------------------------------
__global__ void agg_kernel(const float* __restrict__ h_ext, int use_ext,
                           const int*   __restrict__ in_idx,
                           const float* __restrict__ in_msk,
                           const int*   __restrict__ out_idx,
                           const float* __restrict__ out_msk) {
    const float* h_src = use_ext ? h_ext : g_h;
    __shared__ int   s_idx[2][4][KK];
    __shared__ float s_msk[2][4][KK];

    int tid = threadIdx.x;          // 128 threads: 4 warps = 4 nodes
    int w = tid >> 5;
    int lane = tid & 31;
    int bn = blockIdx.x * 4 + w;    // global node row (b*N + n)

    // stage indices + masks
    {
        int node = blockIdx.x * 4 + w;
        s_idx[0][w][lane] = in_idx [node * KK + lane];
        s_msk[0][w][lane] = in_msk [node * KK + lane];
        s_idx[1][w][lane] = out_idx[node * KK + lane];
        s_msk[1][w][lane] = out_msk[node * KK + lane];
    }
    __syncthreads();

    int base_b = (bn / NN) * NN;    // batch row offset
    const float4* h4 = (const float4*)h_src;

    float4 ai = make_float4(0.f, 0.f, 0.f, 0.f);
    float4 ao = make_float4(0.f, 0.f, 0.f, 0.f);

#pragma unroll 8
    for (int k = 0; k < KK; k++) {
        int   ji = s_idx[0][w][k];
        float mi = s_msk[0][w][k];
        int   jo = s_idx[1][w][k];
        float mo = s_msk[1][w][k];
        float4 vi = h4[(size_t)(base_b + ji) * 32 + lane];
        float4 vo = h4[(size_t)(base_b + jo) * 32 + lane];
        ai.x += mi * vi.x; ai.y += mi * vi.y; ai.z += mi * vi.z; ai.w += mi * vi.w;
        ao.x += mo * vo.x; ao.y += mo * vo.y; ao.z += mo * vo.z; ao.w += mo * vo.w;
    }

    float4* X4 = (float4*)g_X;
    size_t rb = (size_t)bn * 96;          // 384 floats = 96 float4
    X4[rb + lane]      = ai;
    X4[rb + 32 + lane] = ao;
    X4[rb + 64 + lane] = h4[(size_t)bn * 32 + lane];
}

// ---------------------------------------------------------------------------
// Fused GEMM (16000x384 @ 384x[128d x 4g]) + LSTM cell update.
// Block: 256 threads, tile BM=64 rows x 32 d-columns x 4 gates.
// Thread: 8 rows x 1 d x 4 gates = 32 fp32 accumulators.
// ---------------------------------------------------------------------------
__device__ __forceinline__ float sigf(float x) {
    return 1.0f / (1.0f + expf(-x));
}

__global__ void __launch_bounds__(256, 4)
gemm_lstm_kernel(const float* __restrict__ bias,
                 const float* __restrict__ c_ext,
                 float* __restrict__ h_final,
                 int layer) {
    const float* c_src = layer ? g_c : c_ext;
    float* c_dst = g_c;
    float* h_dst = layer ? h_final : g_h;

    __shared__ float Xs[32][68];    // [kk][m], padded: kk*68 keeps 16B align
    __shared__ float Ws[32][132];   // [kk][d*4+g], padded row

    int tid = threadIdx.x;
    int lane = tid & 31;            // d within tile
    int mg = tid >> 5;              // row group 0..7
    int m_base = blockIdx.x * 64;
    int d0 = blockIdx.y * 32;

    float acc[8][4];
#pragma unroll
    for (int r = 0; r < 8; r++)
#pragma unroll
        for (int g = 0; g < 4; g++) acc[r][g] = 0.f;

    for (int kb = 0; kb < KDIM / 32; kb++) {
        // Load X tile (64 rows x 32 k), transposed into Xs[kk][m]
#pragma unroll
        for (int p = 0; p < 2; p++) {
            int m = p * 32 + (tid >> 3);
            int k0 = (tid & 7) * 4;
            float4 v = *(const float4*)(g_X + (size_t)(m_base + m) * KDIM + kb * 32 + k0);
            Xs[k0 + 0][m] = v.x;
            Xs[k0 + 1][m] = v.y;
            Xs[k0 + 2][m] = v.z;
            Xs[k0 + 3][m] = v.w;
        }
        // Load W tile (32 k-rows x 128 packed (d,g)) straight copy
#pragma unroll
        for (int p = 0; p < 4; p++) {
            int r = p * 8 + (tid >> 5);
            int c = (tid & 31) * 4;
            float4 wv = *(const float4*)(g_Wp + (size_t)(kb * 32 + r) * GD + d0 * 4 + c);
            *(float4*)&Ws[r][c] = wv;
        }
        __syncthreads();

#pragma unroll
        for (int kk = 0; kk < 32; kk++) {
            float4 wv = *(const float4*)&Ws[kk][lane * 4];   // gates 0..3 for this d
            float4 xa = *(const float4*)&Xs[kk][mg * 8];     // rows 0..3 (broadcast)
            float4 xb = *(const float4*)&Xs[kk][mg * 8 + 4]; // rows 4..7
            float xr[8] = {xa.x, xa.y, xa.z, xa.w, xb.x, xb.y, xb.z, xb.w};
#pragma unroll
            for (int r = 0; r < 8; r++) {
                acc[r][0] += xr[r] * wv.x;
                acc[r][1] += xr[r] * wv.y;
                acc[r][2] += xr[r] * wv.z;
                acc[r][3] += xr[r] * wv.w;
            }
        }
        __syncthreads();
    }

    // Epilogue: LSTM gate math. Gate order: i, o, f, cell
    int d = d0 + lane;
    float b0 = bias[0 * HH + d];
    float b1 = bias[1 * HH + d];
    float b2 = bias[2 * HH + d];
    float b3 = bias[3 * HH + d];

#pragma unroll
    for (int r = 0; r < 8; r++) {
        int m = m_base + mg * 8 + r;
        size_t off = (size_t)m * HH + d;
        float ig = sigf(acc[r][0] + b0);
        float og = sigf(acc[r][1] + b1);
        float fg = sigf(acc[r][2] + b2);
        float gg = tanhf(acc[r][3] + b3);
        float cn = fg * c_src[off] + ig * gg;
        c_dst[off] = cn;
        h_dst[off] = og * tanhf(cn);
    }
}

// ---------------------------------------------------------------------------
extern "C" void kernel_launch(void* const* d_in, const int* in_sizes, int n_in,
                              void* d_out, int out_size) {
    const float* node_hidden = (const float*)d_in[0];
    const float* cell        = (const float*)d_in[1];
    const float* w_in        = (const float*)d_in[2];
    const float* w_out       = (const float*)d_in[3];
    const float* u_in        = (const float*)d_in[4];
    const float* u_out       = (const float*)d_in[5];
    const float* b           = (const float*)d_in[6];
    const float* in_msk      = (const float*)d_in[7];
    const float* out_msk     = (const float*)d_in[8];
    const int*   in_idx      = (const int*)d_in[9];
    const int*   out_idx     = (const int*)d_in[10];
    // d_in[11] = layer_num (always 2 for this problem)
    float* out = (float*)d_out;

    prep_kernel<<<(KDIM * GD) / 256, 256>>>(w_in, w_out, u_in, u_out);

    dim3 ggrid(MM / 64, HH / 32);

    // Layer 1: h from external input, c from external cell
    agg_kernel<<<MM / 4, 128>>>(node_hidden, 1, in_idx, in_msk, out_idx, out_msk);
    gemm_lstm_kernel<<<ggrid, 256>>>(b, cell, out, 0);

    // Layer 2: h from g_h, c from g_c, final h -> d_out
    agg_kernel<<<MM / 4, 128>>>(nullptr, 0, in_idx, in_msk, out_idx, out_msk);
    gemm_lstm_kernel<<<ggrid, 256>>>(b, nullptr, out, 1);
}

// round 2
// speedup vs baseline: 1.3115x; 1.3115x over previous
#include <cuda_runtime.h>
#include <math.h>

// Problem constants (fixed by setup_inputs)
#define BB 8
#define NN 2000
#define HH 128
#define KK 32
#define MM (BB * NN)        // 16000 rows
#define KDIM 384            // concat [in_agg | out_agg | h]
#define GD 512              // 128 d * 4 gates

#define XROW 256            // duplicated X smem row (2 floats per m)
#define WROW 128            // W smem row

typedef unsigned long long ull;

// packed f32x2 FMA: d = a*b + d (componentwise), 2 FMA per lane per instr
#define FMA2(d, a, b) \
    asm("fma.rn.f32x2 %0, %1, %2, %0;" : "+l"(d) : "l"(a), "l"(b))

// Scratch (device globals; no allocation allowed)
__device__ float g_X[MM * KDIM];     // concatenated GEMM input per layer
__device__ float g_Wp[KDIM * GD];    // W_cat in [k][d*4+g] layout
__device__ float g_h[MM * HH];       // h after layer 1
__device__ float g_c[MM * HH];       // cell state scratch

// ---------------------------------------------------------------------------
// Build W_cat[k][d*4+g]:
//   k in [0,128)   -> w_in[g][k][d]
//   k in [128,256) -> w_out[g][k-128][d]
//   k in [256,384) -> u_in[g][k-256][d] + u_out[g][k-256][d]
// ---------------------------------------------------------------------------
__global__ void prep_kernel(const float* __restrict__ w_in,
                            const float* __restrict__ w_out,
                            const float* __restrict__ u_in,
                            const float* __restrict__ u_out) {
    int idx = blockIdx.x * blockDim.x + threadIdx.x;   // 196608 exact
    int k = idx >> 9;
    int rem = idx & 511;
    int d = rem >> 2;
    int g = rem & 3;
    float v;
    if (k < 128) {
        v = w_in[(g * 128 + k) * 128 + d];
    } else if (k < 256) {
        v = w_out[(g * 128 + (k - 128)) * 128 + d];
    } else {
        int kk = k - 256;
        v = u_in[(g * 128 + kk) * 128 + d] + u_out[(g * 128 + kk) * 128 + d];
    }
    g_Wp[idx] = v;
}

// ---------------------------------------------------------------------------
// Aggregation: one warp per node (unchanged — measured at the L2 roofline).
// ---------------------------------------------------------------------------
__global__ void agg_kernel(const float* __restrict__ h_ext, int use_ext,
                           const int*   __restrict__ in_idx,
                           const float* __restrict__ in_msk,
                           const int*   __restrict__ out_idx,
                           const float* __restrict__ out_msk) {
    const float* h_src = use_ext ? h_ext : g_h;
    __shared__ int   s_idx[2][4][KK];
    __shared__ float s_msk[2][4][KK];

    int tid = threadIdx.x;          // 128 threads: 4 warps = 4 nodes
    int w = tid >> 5;
    int lane = tid & 31;
    int bn = blockIdx.x * 4 + w;

    {
        int node = blockIdx.x * 4 + w;
        s_idx[0][w][lane] = in_idx [node * KK + lane];
        s_msk[0][w][lane] = in_msk [node * KK + lane];
        s_idx[1][w][lane] = out_idx[node * KK + lane];
        s_msk[1][w][lane] = out_msk[node * KK + lane];
    }
    __syncthreads();

    int base_b = (bn / NN) * NN;
    const float4* h4 = (const float4*)h_src;

    float4 ai = make_float4(0.f, 0.f, 0.f, 0.f);
    float4 ao = make_float4(0.f, 0.f, 0.f, 0.f);

#pragma unroll 8
    for (int k = 0; k < KK; k++) {
        int   ji = s_idx[0][w][k];
        float mi = s_msk[0][w][k];
        int   jo = s_idx[1][w][k];
        float mo = s_msk[1][w][k];
        float4 vi = h4[(size_t)(base_b + ji) * 32 + lane];
        float4 vo = h4[(size_t)(base_b + jo) * 32 + lane];
        ai.x += mi * vi.x; ai.y += mi * vi.y; ai.z += mi * vi.z; ai.w += mi * vi.w;
        ao.x += mo * vo.x; ao.y += mo * vo.y; ao.z += mo * vo.z; ao.w += mo * vo.w;
    }

    float4* X4 = (float4*)g_X;
    size_t rb = (size_t)bn * 96;          // 384 floats = 96 float4
    X4[rb + lane]      = ai;
    X4[rb + 32 + lane] = ao;
    X4[rb + 64 + lane] = h4[(size_t)bn * 32 + lane];
}

// ---------------------------------------------------------------------------
// Fused GEMM (16000x384 @ 384x512) + LSTM, packed-f32x2 mainloop.
// Block 256 threads, tile 128 rows x 128 cols (32 d x 4 gates).
// Thread: 8 rows x 8 cols (as 4 f32x2 col-pairs) = 32 FFMA2 per k-step.
// Col mapping: cols {tx*4+0..3} = gates of d_a=by*32+tx,
//              cols {64+tx*4+0..3} = gates of d_b=by*32+16+tx.
// X is stored duplicated in smem so the f32x2 X operand is (x, x).
// ---------------------------------------------------------------------------
__device__ __forceinline__ float sigf(float x) {
    return 1.0f / (1.0f + expf(-x));
}

__global__ void __launch_bounds__(256, 2)
gemm_lstm_kernel(const float* __restrict__ bias,
                 const float* __restrict__ c_ext,
                 float* __restrict__ h_final,
                 int layer) {
    const float* c_src = layer ? g_c : c_ext;
    float* c_dst = g_c;
    float* h_dst = layer ? h_final : g_h;

    __shared__ float Xs[16 * XROW];   // [k][2*m] duplicated
    __shared__ float Ws[16 * WROW];   // [k][c]

    int tid = threadIdx.x;
    int tx = tid & 15;
    int ty = tid >> 4;
    int m_base = blockIdx.x * 128;
    int c0 = blockIdx.y * 128;

    ull acc[8][4];
#pragma unroll
    for (int r = 0; r < 8; r++)
#pragma unroll
        for (int p = 0; p < 4; p++) acc[r][p] = 0ull;

    // loader lanes
    int lxm = tid >> 1;               // 128 rows, 2 threads per row
    int lxk = (tid & 1) * 8;          // k offset 0 or 8
    int lwr = tid >> 4;               // 16 k-rows
    int lwc = (tid & 15) * 8;         // 128 cols, 8 per thread

    const float* Xg = g_X + (size_t)(m_base + lxm) * KDIM + lxk;
    const float* Wg = g_Wp + (size_t)lwr * GD + c0 + lwc;

    float4 xa = *(const float4*)(Xg);
    float4 xb = *(const float4*)(Xg + 4);
    float4 wa = *(const float4*)(Wg);
    float4 wb = *(const float4*)(Wg + 4);

    for (int kb = 0; kb < KDIM / 16; kb++) {
        // stage current tile to smem
        {
            float2* xd = (float2*)&Xs[lxk * XROW + 2 * lxm];
            xd[0 * (XROW / 2)] = make_float2(xa.x, xa.x);
            xd[1 * (XROW / 2)] = make_float2(xa.y, xa.y);
            xd[2 * (XROW / 2)] = make_float2(xa.z, xa.z);
            xd[3 * (XROW / 2)] = make_float2(xa.w, xa.w);
            xd[4 * (XROW / 2)] = make_float2(xb.x, xb.x);
            xd[5 * (XROW / 2)] = make_float2(xb.y, xb.y);
            xd[6 * (XROW / 2)] = make_float2(xb.z, xb.z);
            xd[7 * (XROW / 2)] = make_float2(xb.w, xb.w);
            *(float4*)&Ws[lwr * WROW + lwc] = wa;
            *(float4*)&Ws[lwr * WROW + lwc + 4] = wb;
        }
        __syncthreads();

        // prefetch next tile into registers
        if (kb < KDIM / 16 - 1) {
            const float* Xn = Xg + (kb + 1) * 16;
            const float* Wn = Wg + (size_t)(kb + 1) * 16 * GD;
            xa = *(const float4*)(Xn);
            xb = *(const float4*)(Xn + 4);
            wa = *(const float4*)(Wn);
            wb = *(const float4*)(Wn + 4);
        }

        // compute
#pragma unroll
        for (int kk = 0; kk < 16; kk++) {
            const ull* xr = (const ull*)&Xs[kk * XROW + ty * 16];
            ull x0 = xr[0], x1 = xr[1], x2 = xr[2], x3 = xr[3];
            ull x4 = xr[4], x5 = xr[5], x6 = xr[6], x7 = xr[7];
            ulonglong2 wA = *(const ulonglong2*)&Ws[kk * WROW + tx * 4];
            ulonglong2 wB = *(const ulonglong2*)&Ws[kk * WROW + 64 + tx * 4];
            FMA2(acc[0][0], x0, wA.x); FMA2(acc[0][1], x0, wA.y);
            FMA2(acc[0][2], x0, wB.x); FMA2(acc[0][3], x0, wB.y);
            FMA2(acc[1][0], x1, wA.x); FMA2(acc[1][1], x1, wA.y);
            FMA2(acc[1][2], x1, wB.x); FMA2(acc[1][3], x1, wB.y);
            FMA2(acc[2][0], x2, wA.x); FMA2(acc[2][1], x2, wA.y);
            FMA2(acc[2][2], x2, wB.x); FMA2(acc[2][3], x2, wB.y);
            FMA2(acc[3][0], x3, wA.x); FMA2(acc[3][1], x3, wA.y);
            FMA2(acc[3][2], x3, wB.x); FMA2(acc[3][3], x3, wB.y);
            FMA2(acc[4][0], x4, wA.x); FMA2(acc[4][1], x4, wA.y);
            FMA2(acc[4][2], x4, wB.x); FMA2(acc[4][3], x4, wB.y);
            FMA2(acc[5][0], x5, wA.x); FMA2(acc[5][1], x5, wA.y);
            FMA2(acc[5][2], x5, wB.x); FMA2(acc[5][3], x5, wB.y);
            FMA2(acc[6][0], x6, wA.x); FMA2(acc[6][1], x6, wA.y);
            FMA2(acc[6][2], x6, wB.x); FMA2(acc[6][3], x6, wB.y);
            FMA2(acc[7][0], x7, wA.x); FMA2(acc[7][1], x7, wA.y);
            FMA2(acc[7][2], x7, wB.x); FMA2(acc[7][3], x7, wB.y);
        }
        __syncthreads();
    }

    // Epilogue: LSTM gate math. Gate order in cols: i, o, f, cell
    int dA = blockIdx.y * 32 + tx;
    int dB = dA + 16;
    float bA0 = bias[0 * HH + dA], bA1 = bias[1 * HH + dA];
    float bA2 = bias[2 * HH + dA], bA3 = bias[3 * HH + dA];
    float bB0 = bias[0 * HH + dB], bB1 = bias[1 * HH + dB];
    float bB2 = bias[2 * HH + dB], bB3 = bias[3 * HH + dB];

#pragma unroll
    for (int r = 0; r < 8; r++) {
        int m = m_base + ty * 8 + r;
        size_t offA = (size_t)m * HH + dA;
        size_t offB = (size_t)m * HH + dB;

        float iA = __uint_as_float((unsigned)(acc[r][0]));
        float oA = __uint_as_float((unsigned)(acc[r][0] >> 32));
        float fA = __uint_as_float((unsigned)(acc[r][1]));
        float gA = __uint_as_float((unsigned)(acc[r][1] >> 32));
        float iB = __uint_as_float((unsigned)(acc[r][2]));
        float oB = __uint_as_float((unsigned)(acc[r][2] >> 32));
        float fB = __uint_as_float((unsigned)(acc[r][3]));
        float gB = __uint_as_float((unsigned)(acc[r][3] >> 32));

        float igA = sigf(iA + bA0);
        float ogA = sigf(oA + bA1);
        float fgA = sigf(fA + bA2);
        float ggA = tanhf(gA + bA3);
        float cnA = fgA * c_src[offA] + igA * ggA;
        c_dst[offA] = cnA;
        h_dst[offA] = ogA * tanhf(cnA);

        float igB = sigf(iB + bB0);
        float ogB = sigf(oB + bB1);
        float fgB = sigf(fB + bB2);
        float ggB = tanhf(gB + bB3);
        float cnB = fgB * c_src[offB] + igB * ggB;
        c_dst[offB] = cnB;
        h_dst[offB] = ogB * tanhf(cnB);
    }
}

// ---------------------------------------------------------------------------
extern "C" void kernel_launch(void* const* d_in, const int* in_sizes, int n_in,
                              void* d_out, int out_size) {
    const float* node_hidden = (const float*)d_in[0];
    const float* cell        = (const float*)d_in[1];
    const float* w_in        = (const float*)d_in[2];
    const float* w_out       = (const float*)d_in[3];
    const float* u_in        = (const float*)d_in[4];
    const float* u_out       = (const float*)d_in[5];
    const float* b           = (const float*)d_in[6];
    const float* in_msk      = (const float*)d_in[7];
    const float* out_msk     = (const float*)d_in[8];
    const int*   in_idx      = (const int*)d_in[9];
    const int*   out_idx     = (const int*)d_in[10];
    float* out = (float*)d_out;

    prep_kernel<<<(KDIM * GD) / 256, 256>>>(w_in, w_out, u_in, u_out);

    dim3 ggrid(MM / 128, GD / 128);   // 125 x 4

    // Layer 1
    agg_kernel<<<MM / 4, 128>>>(node_hidden, 1, in_idx, in_msk, out_idx, out_msk);
    gemm_lstm_kernel<<<ggrid, 256>>>(b, cell, out, 0);

    // Layer 2
    agg_kernel<<<MM / 4, 128>>>(nullptr, 0, in_idx, in_msk, out_idx, out_msk);
    gemm_lstm_kernel<<<ggrid, 256>>>(b, nullptr, out, 1);
}

// round 4
// speedup vs baseline: 3.0042x; 2.2907x over previous
#include <cuda_runtime.h>
#include <math.h>
#include <stdint.h>

// Problem constants (fixed by setup_inputs)
#define BB 8
#define NN 2000
#define HH 128
#define KK 32
#define MM (BB * NN)        // 16000 rows
#define KDIM 384            // concat [in_agg | out_agg | h]
#define KB 16               // k per pipeline stage
#define NKB (KDIM / KB)     // 24 stages
#define XS_STRIDE 20        // padded smem row (16 + 4)

// ---- scratch (device globals; no allocation allowed) ----------------------
__device__ float g_X[MM * KDIM];               // X rows, tf32-rounded, [m][k]
__device__ float g_Wt[NKB * 4 * HH * KB];      // [kb][g][d][k], tf32-rounded
__device__ float g_h[MM * HH];                 // h after layer 1 (fp32)
__device__ float g_c[MM * HH];                 // cell scratch (fp32)

// ---- helpers ---------------------------------------------------------------
__device__ __forceinline__ float tf32r(float x) {
    uint32_t y;
    asm("cvt.rna.tf32.f32 %0, %1;" : "=r"(y) : "f"(x));
    return __uint_as_float(y);
}

__device__ __forceinline__ uint32_t smem_u32(const void* p) {
    uint32_t a;
    asm("{ .reg .u64 t; cvta.to.shared.u64 t, %1; cvt.u32.u64 %0, t; }" : "=r"(a) : "l"(p));
    return a;
}

__device__ __forceinline__ void cp16(uint32_t s, const void* g) {
    asm volatile("cp.async.cg.shared.global [%0], [%1], 16;" :: "r"(s), "l"(g));
}

__device__ __forceinline__ void ldm_x4(uint32_t* r, uint32_t addr) {
    asm volatile("ldmatrix.sync.aligned.m8n8.x4.shared.b16 {%0,%1,%2,%3}, [%4];"
                 : "=r"(r[0]), "=r"(r[1]), "=r"(r[2]), "=r"(r[3]) : "r"(addr));
}

__device__ __forceinline__ void mma_tf32(float* c, const uint32_t* a,
                                         uint32_t b0, uint32_t b1) {
    asm volatile(
        "mma.sync.aligned.m16n8k8.row.col.f32.tf32.tf32.f32 "
        "{%0,%1,%2,%3}, {%4,%5,%6,%7}, {%8,%9}, {%0,%1,%2,%3};"
        : "+f"(c[0]), "+f"(c[1]), "+f"(c[2]), "+f"(c[3])
        : "r"(a[0]), "r"(a[1]), "r"(a[2]), "r"(a[3]), "r"(b0), "r"(b1));
}

__device__ __forceinline__ float sigf(float x) { return 1.0f / (1.0f + expf(-x)); }

// ---------------------------------------------------------------------------
// prep: build g_Wt[kb][g][d][k] = tf32( A_g[d][kglob] ), kglob = kb*16 + k
//   A_g[d][kg]: kg<128 -> w_in[g][kg][d]; kg<256 -> w_out[g][kg-128][d];
//               else   -> u_in[g][kg-256][d] + u_out[g][kg-256][d]
// ---------------------------------------------------------------------------
__global__ void prep_kernel(const float* __restrict__ w_in,
                            const float* __restrict__ w_out,
                            const float* __restrict__ u_in,
                            const float* __restrict__ u_out) {
    int idx = blockIdx.x * blockDim.x + threadIdx.x;   // 196608 exact
    int k = idx & 15;
    int d = (idx >> 4) & 127;
    int g = (idx >> 11) & 3;
    int kb = idx >> 13;
    int kg = kb * KB + k;
    float v;
    if (kg < 128) {
        v = w_in[(g * 128 + kg) * 128 + d];
    } else if (kg < 256) {
        v = w_out[(g * 128 + (kg - 128)) * 128 + d];
    } else {
        int kk = kg - 256;
        v = u_in[(g * 128 + kk) * 128 + d] + u_out[(g * 128 + kk) * 128 + d];
    }
    g_Wt[idx] = tf32r(v);
}

// ---------------------------------------------------------------------------
// Aggregation: one warp per node; writes X row (tf32-rounded) to g_X.
// ---------------------------------------------------------------------------
__global__ void agg_kernel(const float* __restrict__ h_ext, int use_ext,
                           const int*   __restrict__ in_idx,
                           const float* __restrict__ in_msk,
                           const int*   __restrict__ out_idx,
                           const float* __restrict__ out_msk) {
    const float* h_src = use_ext ? h_ext : g_h;
    __shared__ int   s_idx[2][4][KK];
    __shared__ float s_msk[2][4][KK];

    int tid = threadIdx.x;          // 128 threads: 4 warps = 4 nodes
    int w = tid >> 5;
    int lane = tid & 31;
    int bn = blockIdx.x * 4 + w;

    {
        int node = blockIdx.x * 4 + w;
        s_idx[0][w][lane] = in_idx [node * KK + lane];
        s_msk[0][w][lane] = in_msk [node * KK + lane];
        s_idx[1][w][lane] = out_idx[node * KK + lane];
        s_msk[1][w][lane] = out_msk[node * KK + lane];
    }
    __syncthreads();

    int base_b = (bn / NN) * NN;
    const float4* h4 = (const float4*)h_src;

    float4 ai = make_float4(0.f, 0.f, 0.f, 0.f);
    float4 ao = make_float4(0.f, 0.f, 0.f, 0.f);

#pragma unroll 8
    for (int k = 0; k < KK; k++) {
        int   ji = s_idx[0][w][k];
        float mi = s_msk[0][w][k];
        int   jo = s_idx[1][w][k];
        float mo = s_msk[1][w][k];
        float4 vi = h4[(size_t)(base_b + ji) * 32 + lane];
        float4 vo = h4[(size_t)(base_b + jo) * 32 + lane];
        ai.x += mi * vi.x; ai.y += mi * vi.y; ai.z += mi * vi.z; ai.w += mi * vi.w;
        ao.x += mo * vo.x; ao.y += mo * vo.y; ao.z += mo * vo.z; ao.w += mo * vo.w;
    }

    float4* X4 = (float4*)g_X;
    size_t rb = (size_t)bn * 96;          // 384 floats = 96 float4

#define TF4(v) make_float4(tf32r((v).x), tf32r((v).y), tf32r((v).z), tf32r((v).w))
    X4[rb + lane]      = TF4(ai);
    X4[rb + 32 + lane] = TF4(ao);
    float4 hv = h4[(size_t)bn * 32 + lane];
    X4[rb + 64 + lane] = TF4(hv);
#undef TF4
}

// ---------------------------------------------------------------------------
// tf32 mma.sync GEMM + fused LSTM.
// Grid (125, 4): CTA tile = 128 m x 32 d x 4 gates. 8 warps of 32m x 16d x 4g.
// K pipelined in 16-wide double-buffered cp.async stages.
// Gate-major B packing: each thread's fragments hold all 4 gates of the same
// (m, d) pair -> fused LSTM epilogue is thread-local.
// ---------------------------------------------------------------------------
__global__ void __launch_bounds__(256, 2)
gemm_lstm_mma(const float* __restrict__ bias,
              const float* __restrict__ c_ext,
              float* __restrict__ h_final,
              int layer) {
    const float* c_src = layer ? g_c : c_ext;
    float* c_dst = g_c;
    float* h_dst = layer ? h_final : g_h;

    __shared__ float Xs[2][128][XS_STRIDE];
    __shared__ float Ws[2][128][XS_STRIDE];

    int tid = threadIdx.x;
    int wid = tid >> 5;
    int lane = tid & 31;
    int m_base = blockIdx.x * 128;
    int d_base = blockIdx.y * 32;
    int m0 = (wid & 3) * 32;
    int d0 = (wid >> 2) * 16;

    uint32_t xs_u = smem_u32(&Xs[0][0][0]);
    uint32_t ws_u = smem_u32(&Ws[0][0][0]);
#define XS_ADDR(s, row, col) (xs_u + (uint32_t)((((s) * 128 + (row)) * XS_STRIDE + (col)) * 4))
#define WS_ADDR(s, row, col) (ws_u + (uint32_t)((((s) * 128 + (row)) * XS_STRIDE + (col)) * 4))

    // loader: 512 cp16 per operand per stage; idx -> row = idx>>2, seg = idx&3
    int l_row = tid >> 2;
    int l_seg = tid & 3;
    int wg = (tid >> 2) >> 5;       // for W: gate of row n
    int wdl = (tid >> 2) & 31;      // d-local of row n

#define LOAD_STAGE(kb, s)                                                       \
    {                                                                           \
        _Pragma("unroll")                                                       \
        for (int i = 0; i < 2; i++) {                                           \
            int row = l_row + i * 64;                                           \
            cp16(XS_ADDR(s, row, l_seg * 4),                                    \
                 g_X + (size_t)(m_base + row) * KDIM + (kb) * KB + l_seg * 4);  \
            int gg = wg + i * 2;                                                \
            cp16(WS_ADDR(s, row, l_seg * 4),                                    \
                 g_Wt + ((size_t)(((kb) * 4 + gg) * HH + d_base + wdl)) * KB    \
                      + l_seg * 4);                                             \
        }                                                                       \
        asm volatile("cp.async.commit_group;" ::: "memory");                    \
    }

    float acc[4][2][2][4];   // [gate][mt][dt][c0..c3]
#pragma unroll
    for (int g = 0; g < 4; g++)
#pragma unroll
        for (int mt = 0; mt < 2; mt++)
#pragma unroll
            for (int dt = 0; dt < 2; dt++)
#pragma unroll
                for (int j = 0; j < 4; j++) acc[g][mt][dt][j] = 0.f;

    // ldmatrix lane mapping
    int frow = ((lane >> 3) & 1) * 8 + (lane & 7);   // row within 16-row block
    int fcol = (lane >> 4) * 4;                      // k sub-column (0 or 4)

    LOAD_STAGE(0, 0);

    for (int kb = 0; kb < NKB; kb++) {
        int s = kb & 1;
        if (kb + 1 < NKB) {
            LOAD_STAGE(kb + 1, s ^ 1);
            asm volatile("cp.async.wait_group 1;" ::: "memory");
        } else {
            asm volatile("cp.async.wait_group 0;" ::: "memory");
        }
        __syncthreads();

#pragma unroll
        for (int k0 = 0; k0 < KB; k0 += 8) {
            uint32_t a[2][4];
            ldm_x4(a[0], XS_ADDR(s, m0 + 0 + frow, k0 + fcol));
            ldm_x4(a[1], XS_ADDR(s, m0 + 16 + frow, k0 + fcol));
            uint32_t b[4][4];
#pragma unroll
            for (int g = 0; g < 4; g++)
                ldm_x4(b[g], WS_ADDR(s, g * 32 + d0 + frow, k0 + fcol));
#pragma unroll
            for (int g = 0; g < 4; g++)
#pragma unroll
                for (int mt = 0; mt < 2; mt++)
#pragma unroll
                    for (int dt = 0; dt < 2; dt++)
                        mma_tf32(acc[g][mt][dt], a[mt], b[g][dt], b[g][dt + 2]);
        }
        __syncthreads();
    }

    // ---- fused LSTM epilogue (gate order: i, o, f, cell) -------------------
    int gid = lane >> 2;
    int tig = lane & 3;

#pragma unroll
    for (int dt = 0; dt < 2; dt++) {
        int d = d_base + d0 + dt * 8 + tig * 2;
        float2 bi = *(const float2*)&bias[0 * HH + d];
        float2 bo = *(const float2*)&bias[1 * HH + d];
        float2 bf = *(const float2*)&bias[2 * HH + d];
        float2 bg = *(const float2*)&bias[3 * HH + d];
#pragma unroll
        for (int mt = 0; mt < 2; mt++) {
#pragma unroll
            for (int rr = 0; rr < 2; rr++) {
                int m = m_base + m0 + mt * 16 + gid + rr * 8;
                size_t off = (size_t)m * HH + d;
                float2 cv = *(const float2*)&c_src[off];

                float i0 = sigf(acc[0][mt][dt][rr * 2 + 0] + bi.x);
                float i1 = sigf(acc[0][mt][dt][rr * 2 + 1] + bi.y);
                float o0 = sigf(acc[1][mt][dt][rr * 2 + 0] + bo.x);
                float o1 = sigf(acc[1][mt][dt][rr * 2 + 1] + bo.y);
                float f0 = sigf(acc[2][mt][dt][rr * 2 + 0] + bf.x);
                float f1 = sigf(acc[2][mt][dt][rr * 2 + 1] + bf.y);
                float g0 = tanhf(acc[3][mt][dt][rr * 2 + 0] + bg.x);
                float g1 = tanhf(acc[3][mt][dt][rr * 2 + 1] + bg.y);

                float cn0 = f0 * cv.x + i0 * g0;
                float cn1 = f1 * cv.y + i1 * g1;
                *(float2*)&c_dst[off] = make_float2(cn0, cn1);
                *(float2*)&h_dst[off] = make_float2(o0 * tanhf(cn0), o1 * tanhf(cn1));
            }
        }
    }
#undef XS_ADDR
#undef WS_ADDR
#undef LOAD_STAGE
}

// ---------------------------------------------------------------------------
extern "C" void kernel_launch(void* const* d_in, const int* in_sizes, int n_in,
                              void* d_out, int out_size) {
    const float* node_hidden = (const float*)d_in[0];
    const float* cell        = (const float*)d_in[1];
    const float* w_in        = (const float*)d_in[2];
    const float* w_out       = (const float*)d_in[3];
    const float* u_in        = (const float*)d_in[4];
    const float* u_out       = (const float*)d_in[5];
    const float* b           = (const float*)d_in[6];
    const float* in_msk      = (const float*)d_in[7];
    const float* out_msk     = (const float*)d_in[8];
    const int*   in_idx      = (const int*)d_in[9];
    const int*   out_idx     = (const int*)d_in[10];
    float* out = (float*)d_out;

    prep_kernel<<<(NKB * 4 * HH * KB) / 256, 256>>>(w_in, w_out, u_in, u_out);

    dim3 ggrid(MM / 128, HH / 32);   // 125 x 4

    // Layer 1
    agg_kernel<<<MM / 4, 128>>>(node_hidden, 1, in_idx, in_msk, out_idx, out_msk);
    gemm_lstm_mma<<<ggrid, 256>>>(b, cell, out, 0);

    // Layer 2
    agg_kernel<<<MM / 4, 128>>>(nullptr, 0, in_idx, in_msk, out_idx, out_msk);
    gemm_lstm_mma<<<ggrid, 256>>>(b, nullptr, out, 1);
}

// round 7
// speedup vs baseline: 4.0303x; 1.3416x over previous
#include <cuda_runtime.h>
#include <cuda_fp16.h>
#include <math.h>
#include <stdint.h>

// Problem constants (fixed by setup_inputs)
#define BB 8
#define NN 2000
#define HH 128
#define KK 32
#define MM (BB * NN)        // 16000 rows
#define KDIM 384            // concat [in_agg | out_agg | h]
#define KB 32               // k per pipeline stage (halfs)
#define NKB (KDIM / KB)     // 12 stages
#define ROWB 80             // padded smem row bytes (64 data + 16 pad)
#define STAGE_B (128 * ROWB)         // 10240 bytes per operand stage
#define SMEM_GEMM (4 * 2 * STAGE_B)  // 81920 bytes

// ---- scratch (device globals; no allocation allowed) ----------------------
__device__ __half g_Xh[MM * KDIM];             // X rows fp16, [m][k]
__device__ __half g_Wh[NKB * 4 * HH * KB];     // [kb][g][d][k] fp16
__device__ float  g_h[MM * HH];                // h after layer 1 (fp32)
__device__ float  g_c[MM * HH];                // cell scratch (fp32)

// ---- helpers ---------------------------------------------------------------
__device__ __forceinline__ uint32_t smem_u32(const void* p) {
    uint32_t a;
    asm("{ .reg .u64 t; cvta.to.shared.u64 t, %1; cvt.u32.u64 %0, t; }" : "=r"(a) : "l"(p));
    return a;
}

__device__ __forceinline__ void cp16(uint32_t s, const void* g) {
    asm volatile("cp.async.cg.shared.global [%0], [%1], 16;" :: "r"(s), "l"(g));
}

__device__ __forceinline__ void ldm_x4(uint32_t* r, uint32_t addr) {
    asm volatile("ldmatrix.sync.aligned.m8n8.x4.shared.b16 {%0,%1,%2,%3}, [%4];"
                 : "=r"(r[0]), "=r"(r[1]), "=r"(r[2]), "=r"(r[3]) : "r"(addr));
}

__device__ __forceinline__ void mma_f16(float* c, const uint32_t* a,
                                        uint32_t b0, uint32_t b1) {
    asm volatile(
        "mma.sync.aligned.m16n8k16.row.col.f32.f16.f16.f32 "
        "{%0,%1,%2,%3}, {%4,%5,%6,%7}, {%8,%9}, {%0,%1,%2,%3};"
        : "+f"(c[0]), "+f"(c[1]), "+f"(c[2]), "+f"(c[3])
        : "r"(a[0]), "r"(a[1]), "r"(a[2]), "r"(a[3]), "r"(b0), "r"(b1));
}

__device__ __forceinline__ float sigf(float x) { return 1.0f / (1.0f + expf(-x)); }

#define WAITG(n) asm volatile("cp.async.wait_group %0;" :: "n"(n) : "memory")

// ---------------------------------------------------------------------------
// prep: g_Wh[kb][g][d][k] = half( A_g[d][kb*32+k] )
// ---------------------------------------------------------------------------
__global__ void prep_kernel(const float* __restrict__ w_in,
                            const float* __restrict__ w_out,
                            const float* __restrict__ u_in,
                            const float* __restrict__ u_out) {
    int idx = blockIdx.x * blockDim.x + threadIdx.x;   // 196608 exact
    int k = idx & 31;
    int d = (idx >> 5) & 127;
    int g = (idx >> 12) & 3;
    int kb = idx >> 14;
    int kg = kb * KB + k;
    float v;
    if (kg < 128) {
        v = w_in[(g * 128 + kg) * 128 + d];
    } else if (kg < 256) {
        v = w_out[(g * 128 + (kg - 128)) * 128 + d];
    } else {
        int kk = kg - 256;
        v = u_in[(g * 128 + kk) * 128 + d] + u_out[(g * 128 + kk) * 128 + d];
    }
    g_Wh[idx] = __float2half_rn(v);
}

// ---------------------------------------------------------------------------
// Aggregation: one warp per node; writes X row (fp16) to g_Xh.
// ---------------------------------------------------------------------------
__global__ void agg_kernel(const float* __restrict__ h_ext, int use_ext,
                           const int*   __restrict__ in_idx,
                           const float* __restrict__ in_msk,
                           const int*   __restrict__ out_idx,
                           const float* __restrict__ out_msk) {
    const float* h_src = use_ext ? h_ext : g_h;
    __shared__ int   s_idx[2][4][KK];
    __shared__ float s_msk[2][4][KK];

    int tid = threadIdx.x;          // 128 threads: 4 warps = 4 nodes
    int w = tid >> 5;
    int lane = tid & 31;
    int bn = blockIdx.x * 4 + w;

    {
        int node = blockIdx.x * 4 + w;
        s_idx[0][w][lane] = in_idx [node * KK + lane];
        s_msk[0][w][lane] = in_msk [node * KK + lane];
        s_idx[1][w][lane] = out_idx[node * KK + lane];
        s_msk[1][w][lane] = out_msk[node * KK + lane];
    }
    __syncthreads();

    int base_b = (bn / NN) * NN;
    const float4* h4 = (const float4*)h_src;

    float4 ai = make_float4(0.f, 0.f, 0.f, 0.f);
    float4 ao = make_float4(0.f, 0.f, 0.f, 0.f);

#pragma unroll 8
    for (int k = 0; k < KK; k++) {
        int   ji = s_idx[0][w][k];
        float mi = s_msk[0][w][k];
        int   jo = s_idx[1][w][k];
        float mo = s_msk[1][w][k];
        float4 vi = h4[(size_t)(base_b + ji) * 32 + lane];
        float4 vo = h4[(size_t)(base_b + jo) * 32 + lane];
        ai.x += mi * vi.x; ai.y += mi * vi.y; ai.z += mi * vi.z; ai.w += mi * vi.w;
        ao.x += mo * vo.x; ao.y += mo * vo.y; ao.z += mo * vo.z; ao.w += mo * vo.w;
    }

    __half2* X2 = (__half2*)(g_Xh + (size_t)bn * KDIM);
    // seg 0: in_agg, seg 1: out_agg, seg 2: h.  lane covers 4 floats = 2 half2
    X2[0 * 64 + lane * 2 + 0] = __floats2half2_rn(ai.x, ai.y);
    X2[0 * 64 + lane * 2 + 1] = __floats2half2_rn(ai.z, ai.w);
    X2[1 * 64 + lane * 2 + 0] = __floats2half2_rn(ao.x, ao.y);
    X2[1 * 64 + lane * 2 + 1] = __floats2half2_rn(ao.z, ao.w);
    float4 hv = h4[(size_t)bn * 32 + lane];
    X2[2 * 64 + lane * 2 + 0] = __floats2half2_rn(hv.x, hv.y);
    X2[2 * 64 + lane * 2 + 1] = __floats2half2_rn(hv.z, hv.w);
}

// ---------------------------------------------------------------------------
// fp16 mma.sync GEMM + fused LSTM.
// Grid (125, 4): CTA tile = 128 m x 32 d x 4 gates. 8 warps of 32m x 16d x 4g.
// K pipelined in 32-wide 4-deep cp.async stages (dynamic smem 80KB).
// Loader: each thread covers 32B per operand per stage (2 x cp16) so the full
// 128 rows x 64B tile is written (R5's bug: only half was).
// ---------------------------------------------------------------------------
__global__ void __launch_bounds__(256, 2)
gemm_lstm_mma(const float* __restrict__ bias,
              const float* __restrict__ c_ext,
              float* __restrict__ h_final,
              int layer) {
    const float* c_src = layer ? g_c : c_ext;
    float* c_dst = g_c;
    float* h_dst = layer ? h_final : g_h;

    extern __shared__ char smem[];
    uint32_t xs_u = smem_u32(smem);
    uint32_t ws_u = xs_u + 4 * STAGE_B;

    int tid = threadIdx.x;
    int wid = tid >> 5;
    int lane = tid & 31;
    int m_base = blockIdx.x * 128;
    int d_base = blockIdx.y * 32;
    int m0 = (wid & 3) * 32;
    int d0 = (wid >> 2) * 16;

// addr helpers: row stride 80B, col in halfs
#define XS_ADDR(s, row, colh) (xs_u + (uint32_t)((s) * STAGE_B + (row) * ROWB + (colh) * 2))
#define WS_ADDR(s, row, colh) (ws_u + (uint32_t)((s) * STAGE_B + (row) * ROWB + (colh) * 2))

    // loader: thread -> row = tid>>1 (0..127), base col = (tid&1)*16 halfs;
    // each thread copies halfs [c, c+8) and [c+8, c+16) => 32B.
    int l_row = tid >> 1;
    int l_colh = (tid & 1) * 16;
    int wg = l_row >> 5;            // gate of W row
    int wdl = l_row & 31;           // d-local of W row

    const __half* xg = g_Xh + (size_t)(m_base + l_row) * KDIM + l_colh;
    const __half* wg_p = g_Wh + ((size_t)(wg * HH) + d_base + wdl) * KB + l_colh;

#define LOAD_STAGE(kb)                                                          \
    {                                                                           \
        int s_ = (kb) & 3;                                                      \
        const __half* xp_ = xg + (size_t)(kb) * KB;                             \
        const __half* wp_ = wg_p + (size_t)(kb) * 4 * HH * KB;                  \
        cp16(XS_ADDR(s_, l_row, l_colh), xp_);                                  \
        cp16(XS_ADDR(s_, l_row, l_colh + 8), xp_ + 8);                          \
        cp16(WS_ADDR(s_, l_row, l_colh), wp_);                                  \
        cp16(WS_ADDR(s_, l_row, l_colh + 8), wp_ + 8);                          \
        asm volatile("cp.async.commit_group;" ::: "memory");                    \
    }

    float acc[4][2][2][4];   // [gate][mt][dt][c0..c3]
#pragma unroll
    for (int g = 0; g < 4; g++)
#pragma unroll
        for (int mt = 0; mt < 2; mt++)
#pragma unroll
            for (int dt = 0; dt < 2; dt++)
#pragma unroll
                for (int j = 0; j < 4; j++) acc[g][mt][dt][j] = 0.f;

    // ldmatrix lane mapping: row within 16-block, 16B col select
    int frow = (lane & 7) + ((lane >> 3) & 1) * 8;
    int fcolh = (lane >> 4) * 8;     // halfs

    LOAD_STAGE(0);
    LOAD_STAGE(1);
    LOAD_STAGE(2);

#pragma unroll
    for (int kb = 0; kb < NKB; kb++) {
        int s = kb & 3;
        if (kb + 3 < NKB) {
            LOAD_STAGE(kb + 3);
            WAITG(3);
        } else if (kb == NKB - 3) {
            WAITG(2);
        } else if (kb == NKB - 2) {
            WAITG(1);
        } else {
            WAITG(0);
        }
        __syncthreads();

#pragma unroll
        for (int ks = 0; ks < 2; ks++) {
            int colh = ks * 16 + fcolh;
            uint32_t a[2][4];
            ldm_x4(a[0], XS_ADDR(s, m0 + 0 + frow, colh));
            ldm_x4(a[1], XS_ADDR(s, m0 + 16 + frow, colh));
            uint32_t b[4][4];
#pragma unroll
            for (int g = 0; g < 4; g++)
                ldm_x4(b[g], WS_ADDR(s, g * 32 + d0 + frow, colh));
#pragma unroll
            for (int g = 0; g < 4; g++)
#pragma unroll
                for (int mt = 0; mt < 2; mt++)
#pragma unroll
                    for (int dt = 0; dt < 2; dt++)
                        mma_f16(acc[g][mt][dt], a[mt], b[g][dt], b[g][dt + 2]);
        }
        __syncthreads();
    }

    // ---- fused LSTM epilogue (gate order: i, o, f, cell) -------------------
    int gid = lane >> 2;
    int tig = lane & 3;

#pragma unroll
    for (int dt = 0; dt < 2; dt++) {
        int d = d_base + d0 + dt * 8 + tig * 2;
        float2 bi = *(const float2*)&bias[0 * HH + d];
        float2 bo = *(const float2*)&bias[1 * HH + d];
        float2 bf = *(const float2*)&bias[2 * HH + d];
        float2 bg = *(const float2*)&bias[3 * HH + d];
#pragma unroll
        for (int mt = 0; mt < 2; mt++) {
#pragma unroll
            for (int rr = 0; rr < 2; rr++) {
                int m = m_base + m0 + mt * 16 + gid + rr * 8;
                size_t off = (size_t)m * HH + d;
                float2 cv = *(const float2*)&c_src[off];

                float i0 = sigf(acc[0][mt][dt][rr * 2 + 0] + bi.x);
                float i1 = sigf(acc[0][mt][dt][rr * 2 + 1] + bi.y);
                float o0 = sigf(acc[1][mt][dt][rr * 2 + 0] + bo.x);
                float o1 = sigf(acc[1][mt][dt][rr * 2 + 1] + bo.y);
                float f0 = sigf(acc[2][mt][dt][rr * 2 + 0] + bf.x);
                float f1 = sigf(acc[2][mt][dt][rr * 2 + 1] + bf.y);
                float g0 = tanhf(acc[3][mt][dt][rr * 2 + 0] + bg.x);
                float g1 = tanhf(acc[3][mt][dt][rr * 2 + 1] + bg.y);

                float cn0 = f0 * cv.x + i0 * g0;
                float cn1 = f1 * cv.y + i1 * g1;
                *(float2*)&c_dst[off] = make_float2(cn0, cn1);
                *(float2*)&h_dst[off] = make_float2(o0 * tanhf(cn0), o1 * tanhf(cn1));
            }
        }
    }
#undef XS_ADDR
#undef WS_ADDR
#undef LOAD_STAGE
}

// ---------------------------------------------------------------------------
extern "C" void kernel_launch(void* const* d_in, const int* in_sizes, int n_in,
                              void* d_out, int out_size) {
    const float* node_hidden = (const float*)d_in[0];
    const float* cell        = (const float*)d_in[1];
    const float* w_in        = (const float*)d_in[2];
    const float* w_out       = (const float*)d_in[3];
    const float* u_in        = (const float*)d_in[4];
    const float* u_out       = (const float*)d_in[5];
    const float* b           = (const float*)d_in[6];
    const float* in_msk      = (const float*)d_in[7];
    const float* out_msk     = (const float*)d_in[8];
    const int*   in_idx      = (const int*)d_in[9];
    const int*   out_idx     = (const int*)d_in[10];
    float* out = (float*)d_out;

    cudaFuncSetAttribute(gemm_lstm_mma,
                         cudaFuncAttributeMaxDynamicSharedMemorySize, SMEM_GEMM);

    prep_kernel<<<(NKB * 4 * HH * KB) / 256, 256>>>(w_in, w_out, u_in, u_out);

    dim3 ggrid(MM / 128, HH / 32);   // 125 x 4

    // Layer 1
    agg_kernel<<<MM / 4, 128>>>(node_hidden, 1, in_idx, in_msk, out_idx, out_msk);
    gemm_lstm_mma<<<ggrid, 256, SMEM_GEMM>>>(b, cell, out, 0);

    // Layer 2
    agg_kernel<<<MM / 4, 128>>>(nullptr, 0, in_idx, in_msk, out_idx, out_msk);
    gemm_lstm_mma<<<ggrid, 256, SMEM_GEMM>>>(b, nullptr, out, 1);
}